// round 13
// baseline (speedup 1.0000x reference)
#include <cuda_runtime.h>
#include <math.h>

#define BB 512
#define TT 1024
#define FF 8
#define H1 70
#define H1P 72
#define H2 21
#define H2P 24
#define G2 84
#define IN2 140
#define IN2P 144
#define D1 30
#define D2 20
#define H22 42
#define GROWS 64

typedef unsigned long long u64;

// Scratch (allocation-free rule: __device__ globals)
__device__ float g_h1[(size_t)BB * TT * IN2];            // layer-1 bi-output
__device__ float g_h2[(size_t)BB * TT * H22];            // layer-2 bi-output
__device__ float g_pre2[2ull * BB * TT * G2];            // layer-2 input proj (cell-major, i/f/o pre-scaled by 0.5)

__device__ __forceinline__ float tanha(float x) {
    float y;
    asm("tanh.approx.f32 %0, %1;" : "=f"(y) : "f"(x));
    return y;
}

// ---- packed f32x2 helpers -------------------------------------------------
__device__ __forceinline__ u64 pack2(float lo, float hi) {
    u64 r;
    asm("mov.b64 %0, {%1, %2};" : "=l"(r) : "f"(lo), "f"(hi));
    return r;
}
__device__ __forceinline__ void unpack2(u64 v, float& lo, float& hi) {
    asm("mov.b64 {%0, %1}, %2;" : "=f"(lo), "=f"(hi) : "l"(v));
}
__device__ __forceinline__ void ffma2(u64& d, u64 a, u64 b) {
    asm("fma.rn.f32x2 %0, %1, %2, %0;" : "+l"(d) : "l"(a), "l"(b));
}
__device__ __forceinline__ u64 addf2(u64 a, u64 b) {
    u64 r;
    asm("add.rn.f32x2 %0, %1, %2;" : "=l"(r) : "l"(a), "l"(b));
    return r;
}

// ---------------------------------------------------------------------------
// Layer 1 v2: one CTA per (batch, direction). 576 threads = 72 cells x 8
// lanes. Lane (j, g, e): cell j, gate g (0=i,1=f,2=gg,3=o), k-half e.
// Each thread: ONE gate row, HALF the dot (18 u64 weights = 36 regs ->
// 9 warps/SMSP at occ 2, double R12's latency cover).
// Gate allgather: shfl_xor 1 (k-halves), then 2 / 4 / (2,4) for the other
// three gates; all 8 lanes compute the cell update redundantly.
// Sigmoid-gate rows (i,f,o) pre-scaled by 0.5 at weight load.
// ---------------------------------------------------------------------------
__global__ __launch_bounds__(576, 2) void lstm1_kernel(
    const float* __restrict__ x,
    const float* __restrict__ wih_f, const float* __restrict__ whh_f,
    const float* __restrict__ bih_f, const float* __restrict__ bhh_f,
    const float* __restrict__ wih_b, const float* __restrict__ whh_b,
    const float* __restrict__ bih_b, const float* __restrict__ bhh_b)
{
    __shared__ __align__(16) float xs[TT * FF];     // 32 KB
    __shared__ __align__(16) float hs[2][H1P];

    const int tid = threadIdx.x;
    const int b   = blockIdx.x;
    const int dir = blockIdx.y;

    const float* wih = dir ? wih_b : wih_f;
    const float* whh = dir ? whh_b : whh_f;
    const float* bih = dir ? bih_b : bih_f;
    const float* bhh = dir ? bhh_b : bhh_f;

    for (int i = tid; i < TT * FF; i += 576)
        xs[i] = x[(size_t)b * TT * FF + i];
    if (tid < H1P) { hs[0][tid] = 0.0f; hs[1][tid] = 0.0f; }

    const int idx = tid >> 1;        // gate-cell 0..287
    const int e   = tid & 1;         // k half
    const int g   = idx & 3;         // gate
    const int j   = idx >> 2;        // cell 0..71
    const bool act = (j < H1);
    const int gv  = act ? (g * H1 + j) : 0;
    const float sc = (g == 2) ? 1.0f : 0.5f;     // tanh gate unscaled
    const bool godd = (g & 1);
    const bool gb1  = (g & 2);

    u64 wh[18];
    #pragma unroll
    for (int k = 0; k < 18; k++) {
        const int c0 = 36 * e + 2 * k, c1 = c0 + 1;
        wh[k] = pack2(sc * ((c0 < H1) ? whh[gv * H1 + c0] : 0.0f),
                      sc * ((c1 < H1) ? whh[gv * H1 + c1] : 0.0f));
    }
    u64 xw[2];
    #pragma unroll
    for (int k = 0; k < 2; k++) {
        const int c0 = 4 * e + 2 * k;
        xw[k] = pack2(sc * wih[gv * FF + c0], sc * wih[gv * FF + c0 + 1]);
    }
    const float bias = (e == 0) ? sc * (bih[gv] + bhh[gv]) : 0.0f;

    float c = 0.0f;
    int cur = 0;
    const int step = dir ? -1 : 1;
    const int tt0 = dir ? (TT - 1) : 0;
    const float* xp = &xs[tt0 * FF + 4 * e];
    float* optr = &g_h1[((size_t)b * TT + tt0) * IN2 + dir * H1 + j];
    const int xstep = step * FF;
    const long ostep = (long)step * IN2;
    __syncthreads();

    // De-phase odd CTAs so co-resident CTAs' tails interleave.
    if (b & 1) {
        float d = bias + 1.3f;
        #pragma unroll
        for (int i = 0; i < 200; i++) d = fmaf(d, 0.99991f, 0.00013f);
        if (d == -1234.5678f) hs[0][H1P - 1] = d;   // never true; keeps chain live
    }

    for (int t = 0; t < TT; t++) {
        const ulonglong2 xv = *(const ulonglong2*)xp;
        u64 a0 = pack2(bias, 0.0f), a1 = 0ull;
        ffma2(a0, xw[0], xv.x);
        ffma2(a1, xw[1], xv.y);

        const ulonglong2* hp = (const ulonglong2*)&hs[cur][36 * e];
        #pragma unroll
        for (int k = 0; k < 9; k++) {
            const ulonglong2 hv = hp[k];
            ffma2(a0, wh[2 * k],     hv.x);
            ffma2(a1, wh[2 * k + 1], hv.y);
        }
        float lo, hi;
        unpack2(addf2(a0, a1), lo, hi);
        float s = lo + hi;
        s += __shfl_xor_sync(0xffffffffu, s, 1);     // combine k-halves

        // activate own gate, then allgather activated values across gates
        const float av = (g == 2) ? tanha(s) : fmaf(0.5f, tanha(s), 0.5f);
        const float v1 = __shfl_xor_sync(0xffffffffu, av, 2);   // gate g^1
        const float v2 = __shfl_xor_sync(0xffffffffu, av, 4);   // gate g^2
        const float v3 = __shfl_xor_sync(0xffffffffu, v1, 4);   // gate g^3

        // (i,gg) and (f,o) are gate-xor-2 pairs:
        const float prod = godd ? (v1 * v3) : (av * v2);        // gi*gg
        const float gf = godd ? (gb1 ? v2 : av) : (gb1 ? v3 : v1);
        const float go = godd ? (gb1 ? av : v2) : (gb1 ? v1 : v3);
        c = fmaf(gf, c, prod);
        const float hval = go * tanha(c);

        const int nxt = cur ^ 1;
        if (((tid & 7) == 0) && act) {
            hs[nxt][j] = hval;
            *optr = hval;
        }
        __syncthreads();
        cur = nxt;
        xp += xstep;
        optr += ostep;
    }
}

// ---------------------------------------------------------------------------
// pre2 GEMM v4 (2-way k-split): 168 threads = 84 gates x 2 halves, grid
// (rows/64, 2). Each thread: ONE gate, half the 144-wide dot. One
// shfl_xor(1) combine. Output cell-major [row][j*4+g], i/f/o pre-scaled.
// ---------------------------------------------------------------------------
__global__ __launch_bounds__(168, 2) void pre2_kernel(
    const float* __restrict__ wih_f, const float* __restrict__ bih_f,
    const float* __restrict__ bhh_f,
    const float* __restrict__ wih_b, const float* __restrict__ bih_b,
    const float* __restrict__ bhh_b)
{
    __shared__ __align__(16) float tile[GROWS][IN2P];   // 36.9 KB

    const int tid = threadIdx.x;
    const int dir = blockIdx.y;
    const float* wih = dir ? wih_b : wih_f;
    const float* bih = dir ? bih_b : bih_f;
    const float* bhh = dir ? bhh_b : bhh_f;

    const int idx = tid >> 1;        // gate index = j*4 + g, 0..83
    const int e   = tid & 1;         // k half
    const int g   = idx & 3;
    const int j   = idx >> 2;
    const int gv  = g * H2 + j;      // row in weight matrix
    const float sc = (g == 2) ? 1.0f : 0.5f;   // tanh gate unscaled

    // half of the input weights: padded cols [72e, 72e+72)
    u64 wk[36];
    #pragma unroll
    for (int k = 0; k < 36; k++) {
        const int c0 = 72 * e + 2 * k, c1 = c0 + 1;
        wk[k] = pack2(sc * ((c0 < IN2) ? wih[gv * IN2 + c0] : 0.0f),
                      sc * ((c1 < IN2) ? wih[gv * IN2 + c1] : 0.0f));
    }
    const float bias = (e == 0) ? sc * (bih[gv] + bhh[gv]) : 0.0f;

    const size_t row0 = (size_t)blockIdx.x * GROWS;

    // stage 64 rows (contiguous 64*140 floats, 16B-aligned) into smem
    const float4* src = (const float4*)(g_h1 + row0 * IN2);
    for (int i = tid; i < GROWS * 35; i += 168) {
        const int r = i / 35, cc = i % 35;
        *(float4*)&tile[r][4 * cc] = src[i];
    }
    for (int i = tid; i < GROWS; i += 168) {
        tile[i][140] = 0.0f; tile[i][141] = 0.0f;
        tile[i][142] = 0.0f; tile[i][143] = 0.0f;
    }
    __syncthreads();

    float* outp = g_pre2 + (size_t)dir * ((size_t)BB * TT * G2)
                + row0 * G2 + idx;
    for (int r = 0; r < GROWS; r++) {
        const ulonglong2* in = (const ulonglong2*)&tile[r][72 * e];
        u64 a0 = pack2(bias, 0.0f), a1 = 0ull, a2 = 0ull, a3 = 0ull;
        #pragma unroll
        for (int k = 0; k < 9; k++) {
            const ulonglong2 va = in[2 * k];
            const ulonglong2 vb = in[2 * k + 1];
            ffma2(a0, wk[4 * k + 0], va.x);
            ffma2(a1, wk[4 * k + 1], va.y);
            ffma2(a2, wk[4 * k + 2], vb.x);
            ffma2(a3, wk[4 * k + 3], vb.y);
        }
        float lo, hi;
        unpack2(addf2(addf2(a0, a1), addf2(a2, a3)), lo, hi);
        float s = lo + hi;
        s += __shfl_xor_sync(0xffffffffu, s, 1);   // combine halves
        if (e == 0) outp[(size_t)r * G2] = s;
    }
}

// ---------------------------------------------------------------------------
// Layer 2 recurrence: one WARP per (batch, direction). Lane j < 21 owns cell
// j (4 gate dots of length 21, sigmoid rows half-scaled). pre2 read as one
// float4 per step (cell-major layout), depth-4 prefetch ring.
// ---------------------------------------------------------------------------
__global__ __launch_bounds__(256, 1) void lstm2_kernel(
    const float* __restrict__ whh_f, const float* __restrict__ whh_b)
{
    __shared__ __align__(16) float hsb[8][2][H2P];   // per-warp double-buffered h

    const int lane = threadIdx.x & 31;
    const int w    = threadIdx.x >> 5;
    const int task = blockIdx.x * 8 + w;
    const int b    = task >> 1;
    const int dir  = task & 1;
    const float* whh = dir ? whh_b : whh_f;

    const bool act = (lane < H2);
    const int j = act ? lane : 0;

    // 4 gate rows for cell j; sigmoid rows (g != 2) scaled by 0.5
    u64 wg[4][12];
    #pragma unroll
    for (int g = 0; g < 4; g++) {
        const int r = g * H2 + j;
        const float sc = (g == 2) ? 1.0f : 0.5f;
        #pragma unroll
        for (int k = 0; k < 12; k++) {
            const int c0 = 2 * k, c1 = c0 + 1;
            wg[g][k] = pack2(sc * ((c0 < H2) ? whh[r * H2 + c0] : 0.0f),
                             sc * ((c1 < H2) ? whh[r * H2 + c1] : 0.0f));
        }
    }
    if (lane < H2P) { hsb[w][0][lane] = 0.0f; hsb[w][1][lane] = 0.0f; }
    __syncwarp();

    const int step = dir ? -1 : 1;
    const int tt0  = dir ? (TT - 1) : 0;
    const float* base = g_pre2 + (size_t)dir * ((size_t)BB * TT * G2);

    // depth-4 prefetch ring of pre2 gate quads
    float4 pr[4];
    const float* pfp = base + ((size_t)b * TT + tt0) * G2 + 4 * j;
    const long pstep = (long)step * G2;
    #pragma unroll
    for (int u = 0; u < 4; u++) {
        pr[u] = *(const float4*)pfp;
        pfp += pstep;
    }

    float* op = &g_h2[((size_t)b * TT + tt0) * H22 + dir * H2 + j];
    const long ostep = (long)step * H22;
    float c = 0.0f;
    int cur = 0;

    for (int t0 = 0; t0 < TT; t0 += 4) {
        #pragma unroll
        for (int u = 0; u < 4; u++) {
            const int t = t0 + u;
            const float4 pv = pr[u];
            if (t + 4 < TT) pr[u] = *(const float4*)pfp;
            pfp += pstep;

            const ulonglong2* hp = (const ulonglong2*)&hsb[w][cur][0];
            u64 a0 = 0ull, a1 = 0ull, a2 = 0ull, a3 = 0ull;
            #pragma unroll
            for (int kk = 0; kk < 6; kk++) {
                const ulonglong2 hv = hp[kk];
                ffma2(a0, wg[0][2 * kk],     hv.x);
                ffma2(a0, wg[0][2 * kk + 1], hv.y);
                ffma2(a1, wg[1][2 * kk],     hv.x);
                ffma2(a1, wg[1][2 * kk + 1], hv.y);
                ffma2(a2, wg[2][2 * kk],     hv.x);
                ffma2(a2, wg[2][2 * kk + 1], hv.y);
                ffma2(a3, wg[3][2 * kk],     hv.x);
                ffma2(a3, wg[3][2 * kk + 1], hv.y);
            }
            float lo, hi;
            unpack2(a0, lo, hi); const float ti = pv.x + lo + hi;
            unpack2(a1, lo, hi); const float tf = pv.y + lo + hi;
            unpack2(a2, lo, hi); const float tg = pv.z + lo + hi;
            unpack2(a3, lo, hi); const float to = pv.w + lo + hi;

            const float gi = fmaf(0.5f, tanha(ti), 0.5f);
            const float gf = fmaf(0.5f, tanha(tf), 0.5f);
            const float gg = tanha(tg);
            const float go = fmaf(0.5f, tanha(to), 0.5f);
            c = fmaf(gf, c, gi * gg);
            const float hval = go * tanha(c);

            const int nxt = cur ^ 1;
            if (act) {
                hsb[w][nxt][lane] = hval;
                *op = hval;
            }
            __syncwarp();
            cur = nxt;
            op += ostep;
        }
    }
}

// ---------------------------------------------------------------------------
// Head MLP (R9-proven form): 42 -> 30 relu -> 20 relu -> 1.
// ---------------------------------------------------------------------------
__global__ __launch_bounds__(128) void head_kernel(
    const float* __restrict__ d1w, const float* __restrict__ d1b,
    const float* __restrict__ d2w, const float* __restrict__ d2b,
    const float* __restrict__ ow,  const float* __restrict__ ob,
    float* __restrict__ out)
{
    __shared__ __align__(16) float sv[128 * H22];
    __shared__ __align__(8) float w1[D1 * H22];
    __shared__ float b1[D1];
    __shared__ __align__(8) float w2[D2 * D1];
    __shared__ float b2[D2];
    __shared__ float wo[D2];
    __shared__ float obias;

    const int tid = threadIdx.x;
    const size_t base = (size_t)blockIdx.x * 128 * H22;

    for (int i = tid; i < 128 * H22; i += 128) sv[i] = g_h2[base + i];
    for (int i = tid; i < D1 * H22; i += 128) w1[i] = d1w[i];
    if (tid < D1) b1[tid] = d1b[tid];
    for (int i = tid; i < D2 * D1; i += 128) w2[i] = d2w[i];
    if (tid < D2) { b2[tid] = d2b[tid]; wo[tid] = ow[tid]; }
    if (tid == 0) obias = ob[0];
    __syncthreads();

    u64 v[21];
    const u64* svr = (const u64*)&sv[tid * H22];
    #pragma unroll
    for (int k = 0; k < 21; k++) v[k] = svr[k];

    float a1[D1];
    #pragma unroll
    for (int jj = 0; jj < D1; jj++) {
        const u64* wr = (const u64*)&w1[jj * H22];
        u64 acc0 = pack2(b1[jj], 0.0f), acc1 = 0ull;
        #pragma unroll
        for (int k = 0; k < 21; k += 2) {
            ffma2(acc0, wr[k], v[k]);
            if (k + 1 < 21) ffma2(acc1, wr[k + 1], v[k + 1]);
        }
        float lo, hi;
        unpack2(addf2(acc0, acc1), lo, hi);
        a1[jj] = fmaxf(lo + hi, 0.0f);
    }
    u64 a1p[15];
    #pragma unroll
    for (int k = 0; k < 15; k++) a1p[k] = pack2(a1[2 * k], a1[2 * k + 1]);

    float a2[D2];
    #pragma unroll
    for (int jj = 0; jj < D2; jj++) {
        const u64* wr = (const u64*)&w2[jj * D1];
        u64 acc0 = pack2(b2[jj], 0.0f), acc1 = 0ull;
        #pragma unroll
        for (int k = 0; k < 15; k += 2) {
            ffma2(acc0, wr[k], a1p[k]);
            if (k + 1 < 15) ffma2(acc1, wr[k + 1], a1p[k + 1]);
        }
        float lo, hi;
        unpack2(addf2(acc0, acc1), lo, hi);
        a2[jj] = fmaxf(lo + hi, 0.0f);
    }
    float o = obias;
    #pragma unroll
    for (int k = 0; k < D2; k++) o = fmaf(wo[k], a2[k], o);

    out[(size_t)blockIdx.x * 128 + tid] = o;
}

// ---------------------------------------------------------------------------
extern "C" void kernel_launch(void* const* d_in, const int* in_sizes, int n_in,
                              void* d_out, int out_size)
{
    const float* x       = (const float*)d_in[0];
    const float* wih1_f  = (const float*)d_in[1];
    const float* whh1_f  = (const float*)d_in[2];
    const float* bih1_f  = (const float*)d_in[3];
    const float* bhh1_f  = (const float*)d_in[4];
    const float* wih1_b  = (const float*)d_in[5];
    const float* whh1_b  = (const float*)d_in[6];
    const float* bih1_b  = (const float*)d_in[7];
    const float* bhh1_b  = (const float*)d_in[8];
    const float* wih2_f  = (const float*)d_in[9];
    const float* whh2_f  = (const float*)d_in[10];
    const float* bih2_f  = (const float*)d_in[11];
    const float* bhh2_f  = (const float*)d_in[12];
    const float* wih2_b  = (const float*)d_in[13];
    const float* whh2_b  = (const float*)d_in[14];
    const float* bih2_b  = (const float*)d_in[15];
    const float* bhh2_b  = (const float*)d_in[16];
    const float* d1w     = (const float*)d_in[17];
    const float* d1b     = (const float*)d_in[18];
    const float* d2w     = (const float*)d_in[19];
    const float* d2b     = (const float*)d_in[20];
    const float* ow      = (const float*)d_in[21];
    const float* obv     = (const float*)d_in[22];
    float* out = (float*)d_out;

    dim3 grid_l1(BB, 2);
    lstm1_kernel<<<grid_l1, 576>>>(x, wih1_f, whh1_f, bih1_f, bhh1_f,
                                   wih1_b, whh1_b, bih1_b, bhh1_b);
    dim3 grid_p2((BB * TT) / GROWS, 2);
    pre2_kernel<<<grid_p2, 168>>>(wih2_f, bih2_f, bhh2_f,
                                  wih2_b, bih2_b, bhh2_b);
    lstm2_kernel<<<(BB * 2) / 8, 256>>>(whh2_f, whh2_b);
    head_kernel<<<(BB * TT) / 128, 128>>>(d1w, d1b, d2w, d2b, ow, obv, out);
}

// round 14
// speedup vs baseline: 1.1557x; 1.1557x over previous
#include <cuda_runtime.h>
#include <math.h>

#define BB 512
#define TT 1024
#define FF 8
#define H1 70
#define H1P 72
#define H2 21
#define H2P 24
#define G2 84
#define IN2 140
#define IN2P 144
#define D1 30
#define D2 20
#define H22 42
#define GROWS 64

typedef unsigned long long u64;

// Scratch (allocation-free rule: __device__ globals)
__device__ float g_h1[(size_t)BB * TT * IN2];            // layer-1 bi-output
__device__ float g_h2[(size_t)BB * TT * H22];            // layer-2 bi-output
__device__ float g_pre2[2ull * BB * TT * G2];            // layer-2 input proj (cell-major, i/f/o pre-scaled by 0.5)

__device__ __forceinline__ float tanha(float x) {
    float y;
    asm("tanh.approx.f32 %0, %1;" : "=f"(y) : "f"(x));
    return y;
}

// ---- packed f32x2 helpers -------------------------------------------------
__device__ __forceinline__ u64 pack2(float lo, float hi) {
    u64 r;
    asm("mov.b64 %0, {%1, %2};" : "=l"(r) : "f"(lo), "f"(hi));
    return r;
}
__device__ __forceinline__ void unpack2(u64 v, float& lo, float& hi) {
    asm("mov.b64 {%0, %1}, %2;" : "=f"(lo), "=f"(hi) : "l"(v));
}
__device__ __forceinline__ void ffma2(u64& d, u64 a, u64 b) {
    asm("fma.rn.f32x2 %0, %1, %2, %0;" : "+l"(d) : "l"(a), "l"(b));
}
__device__ __forceinline__ u64 addf2(u64 a, u64 b) {
    u64 r;
    asm("add.rn.f32x2 %0, %1, %2;" : "=l"(r) : "l"(a), "l"(b));
    return r;
}

// ---------------------------------------------------------------------------
// Layer 1 (R12-proven): one CTA per (batch, direction). 288 threads =
// 72 cells x 4 lanes. Lane (j, p, e): cell j, gate-pair p (p=0 -> i,f ;
// p=1 -> g,o), k-half e. Sigmoid-gate rows (i,f,o) pre-scaled by 0.5.
// ---------------------------------------------------------------------------
__global__ __launch_bounds__(288, 2) void lstm1_kernel(
    const float* __restrict__ x,
    const float* __restrict__ wih_f, const float* __restrict__ whh_f,
    const float* __restrict__ bih_f, const float* __restrict__ bhh_f,
    const float* __restrict__ wih_b, const float* __restrict__ whh_b,
    const float* __restrict__ bih_b, const float* __restrict__ bhh_b)
{
    __shared__ __align__(16) float xs[TT * FF];     // 32 KB
    __shared__ __align__(16) float hs[2][H1P];

    const int tid = threadIdx.x;
    const int b   = blockIdx.x;
    const int dir = blockIdx.y;

    const float* wih = dir ? wih_b : wih_f;
    const float* whh = dir ? whh_b : whh_f;
    const float* bih = dir ? bih_b : bih_f;
    const float* bhh = dir ? bhh_b : bhh_f;

    for (int i = tid; i < TT * FF; i += 288)
        xs[i] = x[(size_t)b * TT * FF + i];
    if (tid < H1P) { hs[0][tid] = 0.0f; hs[1][tid] = 0.0f; }

    const int j = tid >> 2;
    const int p = (tid >> 1) & 1;
    const int e = tid & 1;
    const bool act = (j < H1);
    const int r0 = act ? ((2 * p) * H1 + j) : 0;
    const int r1 = act ? ((2 * p + 1) * H1 + j) : 0;
    const float sc0 = (p == 0) ? 0.5f : 1.0f;   // i scaled, g not
    const float sc1 = 0.5f;                     // f, o scaled

    u64 w0[18], w1[18];
    #pragma unroll
    for (int k = 0; k < 18; k++) {
        const int c0 = 36 * e + 2 * k, c1 = c0 + 1;
        w0[k] = pack2(sc0 * ((c0 < H1) ? whh[r0 * H1 + c0] : 0.0f),
                      sc0 * ((c1 < H1) ? whh[r0 * H1 + c1] : 0.0f));
        w1[k] = pack2(sc1 * ((c0 < H1) ? whh[r1 * H1 + c0] : 0.0f),
                      sc1 * ((c1 < H1) ? whh[r1 * H1 + c1] : 0.0f));
    }
    u64 xw0[2], xw1[2];
    #pragma unroll
    for (int k = 0; k < 2; k++) {
        const int c0 = 4 * e + 2 * k;
        xw0[k] = pack2(sc0 * wih[r0 * FF + c0], sc0 * wih[r0 * FF + c0 + 1]);
        xw1[k] = pack2(sc1 * wih[r1 * FF + c0], sc1 * wih[r1 * FF + c0 + 1]);
    }
    const float bias0 = (e == 0) ? sc0 * (bih[r0] + bhh[r0]) : 0.0f;
    const float bias1 = (e == 0) ? sc1 * (bih[r1] + bhh[r1]) : 0.0f;

    float c = 0.0f;
    int cur = 0;
    const int step = dir ? -1 : 1;
    const int tt0 = dir ? (TT - 1) : 0;
    const float* xp = &xs[tt0 * FF + 4 * e];
    float* optr = &g_h1[((size_t)b * TT + tt0) * IN2 + dir * H1 + j];
    const int xstep = step * FF;
    const long ostep = (long)step * IN2;
    __syncthreads();

    // De-phase odd CTAs so co-resident CTAs' tails interleave.
    if (b & 1) {
        float d = bias0 + 1.3f;
        #pragma unroll
        for (int i = 0; i < 200; i++) d = fmaf(d, 0.99991f, 0.00013f);
        if (d == -1234.5678f) hs[0][H1P - 1] = d;   // never true; keeps chain live
    }

    for (int t = 0; t < TT; t++) {
        const ulonglong2 xv = *(const ulonglong2*)xp;
        u64 a00 = pack2(bias0, 0.0f), a01 = 0ull;
        u64 a10 = pack2(bias1, 0.0f), a11 = 0ull;
        ffma2(a00, xw0[0], xv.x); ffma2(a01, xw0[1], xv.y);
        ffma2(a10, xw1[0], xv.x); ffma2(a11, xw1[1], xv.y);

        const ulonglong2* hp = (const ulonglong2*)&hs[cur][36 * e];
        #pragma unroll
        for (int k = 0; k < 9; k++) {
            const ulonglong2 hv = hp[k];
            ffma2(a00, w0[2 * k],     hv.x);
            ffma2(a01, w0[2 * k + 1], hv.y);
            ffma2(a10, w1[2 * k],     hv.x);
            ffma2(a11, w1[2 * k + 1], hv.y);
        }
        float lo, hi;
        unpack2(addf2(a00, a01), lo, hi);
        float s0 = lo + hi;
        unpack2(addf2(a10, a11), lo, hi);
        float s1 = lo + hi;

        s0 += __shfl_xor_sync(0xffffffffu, s0, 1);   // combine k-halves
        s1 += __shfl_xor_sync(0xffffffffu, s1, 1);

        // activate own gate pair, THEN exchange activated values.
        // p=0: act0=sig(i), act1=sig(f); p=1: act0=tanh(g), act1=sig(o)
        const float act0 = p ? tanha(s0) : fmaf(0.5f, tanha(s0), 0.5f);
        const float act1 = fmaf(0.5f, tanha(s1), 0.5f);
        const float x0 = __shfl_xor_sync(0xffffffffu, act0, 2);
        const float x1 = __shfl_xor_sync(0xffffffffu, act1, 2);

        // gi*gg == act0*x0 in BOTH lanes; only f/o need selects
        const float prod = act0 * x0;
        const float gf = p ? x1 : act1;
        const float go = p ? act1 : x1;
        c = fmaf(gf, c, prod);
        const float hval = go * tanha(c);

        const int nxt = cur ^ 1;
        if (((tid & 3) == 0) && act) {
            hs[nxt][j] = hval;
            *optr = hval;
        }
        __syncthreads();
        cur = nxt;
        xp += xstep;
        optr += ostep;
    }
}

// ---------------------------------------------------------------------------
// pre2 GEMM v5: v4 layout (168 threads = 84 gates x 2 halves, grid
// (rows/64, 2)) at occupancy 3 (reg cap 130 >= ~100 used; smem 111 KB/SM).
// Output cell-major [row][j*4+g], i/f/o rows pre-scaled by 0.5.
// ---------------------------------------------------------------------------
__global__ __launch_bounds__(168, 3) void pre2_kernel(
    const float* __restrict__ wih_f, const float* __restrict__ bih_f,
    const float* __restrict__ bhh_f,
    const float* __restrict__ wih_b, const float* __restrict__ bih_b,
    const float* __restrict__ bhh_b)
{
    __shared__ __align__(16) float tile[GROWS][IN2P];   // 36.9 KB

    const int tid = threadIdx.x;
    const int dir = blockIdx.y;
    const float* wih = dir ? wih_b : wih_f;
    const float* bih = dir ? bih_b : bih_f;
    const float* bhh = dir ? bhh_b : bhh_f;

    const int idx = tid >> 1;        // gate index = j*4 + g, 0..83
    const int e   = tid & 1;         // k half
    const int g   = idx & 3;
    const int j   = idx >> 2;
    const int gv  = g * H2 + j;      // row in weight matrix
    const float sc = (g == 2) ? 1.0f : 0.5f;   // tanh gate unscaled

    // half of the input weights: padded cols [72e, 72e+72)
    u64 wk[36];
    #pragma unroll
    for (int k = 0; k < 36; k++) {
        const int c0 = 72 * e + 2 * k, c1 = c0 + 1;
        wk[k] = pack2(sc * ((c0 < IN2) ? wih[gv * IN2 + c0] : 0.0f),
                      sc * ((c1 < IN2) ? wih[gv * IN2 + c1] : 0.0f));
    }
    const float bias = (e == 0) ? sc * (bih[gv] + bhh[gv]) : 0.0f;

    const size_t row0 = (size_t)blockIdx.x * GROWS;

    // stage 64 rows (contiguous 64*140 floats, 16B-aligned) into smem
    const float4* src = (const float4*)(g_h1 + row0 * IN2);
    for (int i = tid; i < GROWS * 35; i += 168) {
        const int r = i / 35, cc = i % 35;
        *(float4*)&tile[r][4 * cc] = src[i];
    }
    for (int i = tid; i < GROWS; i += 168) {
        tile[i][140] = 0.0f; tile[i][141] = 0.0f;
        tile[i][142] = 0.0f; tile[i][143] = 0.0f;
    }
    __syncthreads();

    float* outp = g_pre2 + (size_t)dir * ((size_t)BB * TT * G2)
                + row0 * G2 + idx;
    for (int r = 0; r < GROWS; r++) {
        const ulonglong2* in = (const ulonglong2*)&tile[r][72 * e];
        u64 a0 = pack2(bias, 0.0f), a1 = 0ull, a2 = 0ull, a3 = 0ull;
        #pragma unroll
        for (int k = 0; k < 9; k++) {
            const ulonglong2 va = in[2 * k];
            const ulonglong2 vb = in[2 * k + 1];
            ffma2(a0, wk[4 * k + 0], va.x);
            ffma2(a1, wk[4 * k + 1], va.y);
            ffma2(a2, wk[4 * k + 2], vb.x);
            ffma2(a3, wk[4 * k + 3], vb.y);
        }
        float lo, hi;
        unpack2(addf2(addf2(a0, a1), addf2(a2, a3)), lo, hi);
        float s = lo + hi;
        s += __shfl_xor_sync(0xffffffffu, s, 1);   // combine halves
        if (e == 0) outp[(size_t)r * G2] = s;
    }
}

// ---------------------------------------------------------------------------
// Layer 2 recurrence: one WARP per (batch, direction). Lane j < 21 owns cell
// j (4 gate dots of length 21, sigmoid rows half-scaled). pre2 read as one
// float4 per step (cell-major layout), depth-4 prefetch ring.
// ---------------------------------------------------------------------------
__global__ __launch_bounds__(256, 1) void lstm2_kernel(
    const float* __restrict__ whh_f, const float* __restrict__ whh_b)
{
    __shared__ __align__(16) float hsb[8][2][H2P];   // per-warp double-buffered h

    const int lane = threadIdx.x & 31;
    const int w    = threadIdx.x >> 5;
    const int task = blockIdx.x * 8 + w;
    const int b    = task >> 1;
    const int dir  = task & 1;
    const float* whh = dir ? whh_b : whh_f;

    const bool act = (lane < H2);
    const int j = act ? lane : 0;

    // 4 gate rows for cell j; sigmoid rows (g != 2) scaled by 0.5
    u64 wg[4][12];
    #pragma unroll
    for (int g = 0; g < 4; g++) {
        const int r = g * H2 + j;
        const float sc = (g == 2) ? 1.0f : 0.5f;
        #pragma unroll
        for (int k = 0; k < 12; k++) {
            const int c0 = 2 * k, c1 = c0 + 1;
            wg[g][k] = pack2(sc * ((c0 < H2) ? whh[r * H2 + c0] : 0.0f),
                             sc * ((c1 < H2) ? whh[r * H2 + c1] : 0.0f));
        }
    }
    if (lane < H2P) { hsb[w][0][lane] = 0.0f; hsb[w][1][lane] = 0.0f; }
    __syncwarp();

    const int step = dir ? -1 : 1;
    const int tt0  = dir ? (TT - 1) : 0;
    const float* base = g_pre2 + (size_t)dir * ((size_t)BB * TT * G2);

    // depth-4 prefetch ring of pre2 gate quads
    float4 pr[4];
    const float* pfp = base + ((size_t)b * TT + tt0) * G2 + 4 * j;
    const long pstep = (long)step * G2;
    #pragma unroll
    for (int u = 0; u < 4; u++) {
        pr[u] = *(const float4*)pfp;
        pfp += pstep;
    }

    float* op = &g_h2[((size_t)b * TT + tt0) * H22 + dir * H2 + j];
    const long ostep = (long)step * H22;
    float c = 0.0f;
    int cur = 0;

    for (int t0 = 0; t0 < TT; t0 += 4) {
        #pragma unroll
        for (int u = 0; u < 4; u++) {
            const int t = t0 + u;
            const float4 pv = pr[u];
            if (t + 4 < TT) pr[u] = *(const float4*)pfp;
            pfp += pstep;

            const ulonglong2* hp = (const ulonglong2*)&hsb[w][cur][0];
            u64 a0 = 0ull, a1 = 0ull, a2 = 0ull, a3 = 0ull;
            #pragma unroll
            for (int kk = 0; kk < 6; kk++) {
                const ulonglong2 hv = hp[kk];
                ffma2(a0, wg[0][2 * kk],     hv.x);
                ffma2(a0, wg[0][2 * kk + 1], hv.y);
                ffma2(a1, wg[1][2 * kk],     hv.x);
                ffma2(a1, wg[1][2 * kk + 1], hv.y);
                ffma2(a2, wg[2][2 * kk],     hv.x);
                ffma2(a2, wg[2][2 * kk + 1], hv.y);
                ffma2(a3, wg[3][2 * kk],     hv.x);
                ffma2(a3, wg[3][2 * kk + 1], hv.y);
            }
            float lo, hi;
            unpack2(a0, lo, hi); const float ti = pv.x + lo + hi;
            unpack2(a1, lo, hi); const float tf = pv.y + lo + hi;
            unpack2(a2, lo, hi); const float tg = pv.z + lo + hi;
            unpack2(a3, lo, hi); const float to = pv.w + lo + hi;

            const float gi = fmaf(0.5f, tanha(ti), 0.5f);
            const float gf = fmaf(0.5f, tanha(tf), 0.5f);
            const float gg = tanha(tg);
            const float go = fmaf(0.5f, tanha(to), 0.5f);
            c = fmaf(gf, c, gi * gg);
            const float hval = go * tanha(c);

            const int nxt = cur ^ 1;
            if (act) {
                hsb[w][nxt][lane] = hval;
                *op = hval;
            }
            __syncwarp();
            cur = nxt;
            op += ostep;
        }
    }
}

// ---------------------------------------------------------------------------
// Head MLP (R9-proven form): 42 -> 30 relu -> 20 relu -> 1.
// ---------------------------------------------------------------------------
__global__ __launch_bounds__(128) void head_kernel(
    const float* __restrict__ d1w, const float* __restrict__ d1b,
    const float* __restrict__ d2w, const float* __restrict__ d2b,
    const float* __restrict__ ow,  const float* __restrict__ ob,
    float* __restrict__ out)
{
    __shared__ __align__(16) float sv[128 * H22];
    __shared__ __align__(8) float w1[D1 * H22];
    __shared__ float b1[D1];
    __shared__ __align__(8) float w2[D2 * D1];
    __shared__ float b2[D2];
    __shared__ float wo[D2];
    __shared__ float obias;

    const int tid = threadIdx.x;
    const size_t base = (size_t)blockIdx.x * 128 * H22;

    for (int i = tid; i < 128 * H22; i += 128) sv[i] = g_h2[base + i];
    for (int i = tid; i < D1 * H22; i += 128) w1[i] = d1w[i];
    if (tid < D1) b1[tid] = d1b[tid];
    for (int i = tid; i < D2 * D1; i += 128) w2[i] = d2w[i];
    if (tid < D2) { b2[tid] = d2b[tid]; wo[tid] = ow[tid]; }
    if (tid == 0) obias = ob[0];
    __syncthreads();

    u64 v[21];
    const u64* svr = (const u64*)&sv[tid * H22];
    #pragma unroll
    for (int k = 0; k < 21; k++) v[k] = svr[k];

    float a1[D1];
    #pragma unroll
    for (int jj = 0; jj < D1; jj++) {
        const u64* wr = (const u64*)&w1[jj * H22];
        u64 acc0 = pack2(b1[jj], 0.0f), acc1 = 0ull;
        #pragma unroll
        for (int k = 0; k < 21; k += 2) {
            ffma2(acc0, wr[k], v[k]);
            if (k + 1 < 21) ffma2(acc1, wr[k + 1], v[k + 1]);
        }
        float lo, hi;
        unpack2(addf2(acc0, acc1), lo, hi);
        a1[jj] = fmaxf(lo + hi, 0.0f);
    }
    u64 a1p[15];
    #pragma unroll
    for (int k = 0; k < 15; k++) a1p[k] = pack2(a1[2 * k], a1[2 * k + 1]);

    float a2[D2];
    #pragma unroll
    for (int jj = 0; jj < D2; jj++) {
        const u64* wr = (const u64*)&w2[jj * D1];
        u64 acc0 = pack2(b2[jj], 0.0f), acc1 = 0ull;
        #pragma unroll
        for (int k = 0; k < 15; k += 2) {
            ffma2(acc0, wr[k], a1p[k]);
            if (k + 1 < 15) ffma2(acc1, wr[k + 1], a1p[k + 1]);
        }
        float lo, hi;
        unpack2(addf2(acc0, acc1), lo, hi);
        a2[jj] = fmaxf(lo + hi, 0.0f);
    }
    float o = obias;
    #pragma unroll
    for (int k = 0; k < D2; k++) o = fmaf(wo[k], a2[k], o);

    out[(size_t)blockIdx.x * 128 + tid] = o;
}

// ---------------------------------------------------------------------------
extern "C" void kernel_launch(void* const* d_in, const int* in_sizes, int n_in,
                              void* d_out, int out_size)
{
    const float* x       = (const float*)d_in[0];
    const float* wih1_f  = (const float*)d_in[1];
    const float* whh1_f  = (const float*)d_in[2];
    const float* bih1_f  = (const float*)d_in[3];
    const float* bhh1_f  = (const float*)d_in[4];
    const float* wih1_b  = (const float*)d_in[5];
    const float* whh1_b  = (const float*)d_in[6];
    const float* bih1_b  = (const float*)d_in[7];
    const float* bhh1_b  = (const float*)d_in[8];
    const float* wih2_f  = (const float*)d_in[9];
    const float* whh2_f  = (const float*)d_in[10];
    const float* bih2_f  = (const float*)d_in[11];
    const float* bhh2_f  = (const float*)d_in[12];
    const float* wih2_b  = (const float*)d_in[13];
    const float* whh2_b  = (const float*)d_in[14];
    const float* bih2_b  = (const float*)d_in[15];
    const float* bhh2_b  = (const float*)d_in[16];
    const float* d1w     = (const float*)d_in[17];
    const float* d1b     = (const float*)d_in[18];
    const float* d2w     = (const float*)d_in[19];
    const float* d2b     = (const float*)d_in[20];
    const float* ow      = (const float*)d_in[21];
    const float* obv     = (const float*)d_in[22];
    float* out = (float*)d_out;

    dim3 grid_l1(BB, 2);
    lstm1_kernel<<<grid_l1, 288>>>(x, wih1_f, whh1_f, bih1_f, bhh1_f,
                                   wih1_b, whh1_b, bih1_b, bhh1_b);
    dim3 grid_p2((BB * TT) / GROWS, 2);
    pre2_kernel<<<grid_p2, 168>>>(wih2_f, bih2_f, bhh2_f,
                                  wih2_b, bih2_b, bhh2_b);
    lstm2_kernel<<<(BB * 2) / 8, 256>>>(whh2_f, whh2_b);
    head_kernel<<<(BB * TT) / 128, 128>>>(d1w, d1b, d2w, d2b, ow, obv, out);
}

// round 15
// speedup vs baseline: 1.1703x; 1.0126x over previous
#include <cuda_runtime.h>
#include <math.h>

#define BB 512
#define TT 1024
#define FF 8
#define H1 70
#define H1P 72
#define H2 21
#define H2P 24
#define G2 84
#define IN2 140
#define IN2P 144
#define D1 30
#define D2 20
#define H22 42
#define GROWS 64

typedef unsigned long long u64;

// Scratch (allocation-free rule: __device__ globals)
__device__ float g_h1[(size_t)BB * TT * IN2];            // layer-1 bi-output
__device__ float g_h2[(size_t)BB * TT * H22];            // layer-2 bi-output
__device__ float g_pre2[2ull * BB * TT * G2];            // layer-2 input proj (cell-major, i/f/o pre-scaled by 0.5)

__device__ __forceinline__ float tanha(float x) {
    float y;
    asm("tanh.approx.f32 %0, %1;" : "=f"(y) : "f"(x));
    return y;
}

// ---- packed f32x2 helpers -------------------------------------------------
__device__ __forceinline__ u64 pack2(float lo, float hi) {
    u64 r;
    asm("mov.b64 %0, {%1, %2};" : "=l"(r) : "f"(lo), "f"(hi));
    return r;
}
__device__ __forceinline__ void unpack2(u64 v, float& lo, float& hi) {
    asm("mov.b64 {%0, %1}, %2;" : "=f"(lo), "=f"(hi) : "l"(v));
}
__device__ __forceinline__ void ffma2(u64& d, u64 a, u64 b) {
    asm("fma.rn.f32x2 %0, %1, %2, %0;" : "+l"(d) : "l"(a), "l"(b));
}
__device__ __forceinline__ u64 addf2(u64 a, u64 b) {
    u64 r;
    asm("add.rn.f32x2 %0, %1, %2;" : "=l"(r) : "l"(a), "l"(b));
    return r;
}

// ---------------------------------------------------------------------------
// Layer 1 (R12-proven): one CTA per (batch, direction). 288 threads =
// 72 cells x 4 lanes. Lane (j, p, e): cell j, gate-pair p (p=0 -> i,f ;
// p=1 -> g,o), k-half e. Sigmoid-gate rows (i,f,o) pre-scaled by 0.5.
// ---------------------------------------------------------------------------
__global__ __launch_bounds__(288, 2) void lstm1_kernel(
    const float* __restrict__ x,
    const float* __restrict__ wih_f, const float* __restrict__ whh_f,
    const float* __restrict__ bih_f, const float* __restrict__ bhh_f,
    const float* __restrict__ wih_b, const float* __restrict__ whh_b,
    const float* __restrict__ bih_b, const float* __restrict__ bhh_b)
{
    __shared__ __align__(16) float xs[TT * FF];     // 32 KB
    __shared__ __align__(16) float hs[2][H1P];

    const int tid = threadIdx.x;
    const int b   = blockIdx.x;
    const int dir = blockIdx.y;

    const float* wih = dir ? wih_b : wih_f;
    const float* whh = dir ? whh_b : whh_f;
    const float* bih = dir ? bih_b : bih_f;
    const float* bhh = dir ? bhh_b : bhh_f;

    for (int i = tid; i < TT * FF; i += 288)
        xs[i] = x[(size_t)b * TT * FF + i];
    if (tid < H1P) { hs[0][tid] = 0.0f; hs[1][tid] = 0.0f; }

    const int j = tid >> 2;
    const int p = (tid >> 1) & 1;
    const int e = tid & 1;
    const bool act = (j < H1);
    const int r0 = act ? ((2 * p) * H1 + j) : 0;
    const int r1 = act ? ((2 * p + 1) * H1 + j) : 0;
    const float sc0 = (p == 0) ? 0.5f : 1.0f;   // i scaled, g not
    const float sc1 = 0.5f;                     // f, o scaled

    u64 w0[18], w1[18];
    #pragma unroll
    for (int k = 0; k < 18; k++) {
        const int c0 = 36 * e + 2 * k, c1 = c0 + 1;
        w0[k] = pack2(sc0 * ((c0 < H1) ? whh[r0 * H1 + c0] : 0.0f),
                      sc0 * ((c1 < H1) ? whh[r0 * H1 + c1] : 0.0f));
        w1[k] = pack2(sc1 * ((c0 < H1) ? whh[r1 * H1 + c0] : 0.0f),
                      sc1 * ((c1 < H1) ? whh[r1 * H1 + c1] : 0.0f));
    }
    u64 xw0[2], xw1[2];
    #pragma unroll
    for (int k = 0; k < 2; k++) {
        const int c0 = 4 * e + 2 * k;
        xw0[k] = pack2(sc0 * wih[r0 * FF + c0], sc0 * wih[r0 * FF + c0 + 1]);
        xw1[k] = pack2(sc1 * wih[r1 * FF + c0], sc1 * wih[r1 * FF + c0 + 1]);
    }
    const float bias0 = (e == 0) ? sc0 * (bih[r0] + bhh[r0]) : 0.0f;
    const float bias1 = (e == 0) ? sc1 * (bih[r1] + bhh[r1]) : 0.0f;

    float c = 0.0f;
    int cur = 0;
    const int step = dir ? -1 : 1;
    const int tt0 = dir ? (TT - 1) : 0;
    const float* xp = &xs[tt0 * FF + 4 * e];
    float* optr = &g_h1[((size_t)b * TT + tt0) * IN2 + dir * H1 + j];
    const int xstep = step * FF;
    const long ostep = (long)step * IN2;
    __syncthreads();

    // De-phase odd CTAs so co-resident CTAs' tails interleave.
    if (b & 1) {
        float d = bias0 + 1.3f;
        #pragma unroll
        for (int i = 0; i < 200; i++) d = fmaf(d, 0.99991f, 0.00013f);
        if (d == -1234.5678f) hs[0][H1P - 1] = d;   // never true; keeps chain live
    }

    for (int t = 0; t < TT; t++) {
        const ulonglong2 xv = *(const ulonglong2*)xp;
        u64 a00 = pack2(bias0, 0.0f), a01 = 0ull;
        u64 a10 = pack2(bias1, 0.0f), a11 = 0ull;
        ffma2(a00, xw0[0], xv.x); ffma2(a01, xw0[1], xv.y);
        ffma2(a10, xw1[0], xv.x); ffma2(a11, xw1[1], xv.y);

        const ulonglong2* hp = (const ulonglong2*)&hs[cur][36 * e];
        #pragma unroll
        for (int k = 0; k < 9; k++) {
            const ulonglong2 hv = hp[k];
            ffma2(a00, w0[2 * k],     hv.x);
            ffma2(a01, w0[2 * k + 1], hv.y);
            ffma2(a10, w1[2 * k],     hv.x);
            ffma2(a11, w1[2 * k + 1], hv.y);
        }
        float lo, hi;
        unpack2(addf2(a00, a01), lo, hi);
        float s0 = lo + hi;
        unpack2(addf2(a10, a11), lo, hi);
        float s1 = lo + hi;

        s0 += __shfl_xor_sync(0xffffffffu, s0, 1);   // combine k-halves
        s1 += __shfl_xor_sync(0xffffffffu, s1, 1);

        // activate own gate pair, THEN exchange activated values.
        // p=0: act0=sig(i), act1=sig(f); p=1: act0=tanh(g), act1=sig(o)
        const float act0 = p ? tanha(s0) : fmaf(0.5f, tanha(s0), 0.5f);
        const float act1 = fmaf(0.5f, tanha(s1), 0.5f);
        const float x0 = __shfl_xor_sync(0xffffffffu, act0, 2);
        const float x1 = __shfl_xor_sync(0xffffffffu, act1, 2);

        // gi*gg == act0*x0 in BOTH lanes; only f/o need selects
        const float prod = act0 * x0;
        const float gf = p ? x1 : act1;
        const float go = p ? act1 : x1;
        c = fmaf(gf, c, prod);
        const float hval = go * tanha(c);

        const int nxt = cur ^ 1;
        if (((tid & 3) == 0) && act) {
            hs[nxt][j] = hval;
            *optr = hval;
        }
        __syncthreads();
        cur = nxt;
        xp += xstep;
        optr += ostep;
    }
}

// ---------------------------------------------------------------------------
// pre2 GEMM v4 (R12-proven): 168 threads = 84 gates x 2 halves, grid
// (rows/64, 2), occupancy 2. One shfl_xor(1) combine. Output cell-major
// [row][j*4+g], i/f/o rows pre-scaled by 0.5.
// ---------------------------------------------------------------------------
__global__ __launch_bounds__(168, 2) void pre2_kernel(
    const float* __restrict__ wih_f, const float* __restrict__ bih_f,
    const float* __restrict__ bhh_f,
    const float* __restrict__ wih_b, const float* __restrict__ bih_b,
    const float* __restrict__ bhh_b)
{
    __shared__ __align__(16) float tile[GROWS][IN2P];   // 36.9 KB

    const int tid = threadIdx.x;
    const int dir = blockIdx.y;
    const float* wih = dir ? wih_b : wih_f;
    const float* bih = dir ? bih_b : bih_f;
    const float* bhh = dir ? bhh_b : bhh_f;

    const int idx = tid >> 1;        // gate index = j*4 + g, 0..83
    const int e   = tid & 1;         // k half
    const int g   = idx & 3;
    const int j   = idx >> 2;
    const int gv  = g * H2 + j;      // row in weight matrix
    const float sc = (g == 2) ? 1.0f : 0.5f;   // tanh gate unscaled

    // half of the input weights: padded cols [72e, 72e+72)
    u64 wk[36];
    #pragma unroll
    for (int k = 0; k < 36; k++) {
        const int c0 = 72 * e + 2 * k, c1 = c0 + 1;
        wk[k] = pack2(sc * ((c0 < IN2) ? wih[gv * IN2 + c0] : 0.0f),
                      sc * ((c1 < IN2) ? wih[gv * IN2 + c1] : 0.0f));
    }
    const float bias = (e == 0) ? sc * (bih[gv] + bhh[gv]) : 0.0f;

    const size_t row0 = (size_t)blockIdx.x * GROWS;

    // stage 64 rows (contiguous 64*140 floats, 16B-aligned) into smem
    const float4* src = (const float4*)(g_h1 + row0 * IN2);
    for (int i = tid; i < GROWS * 35; i += 168) {
        const int r = i / 35, cc = i % 35;
        *(float4*)&tile[r][4 * cc] = src[i];
    }
    for (int i = tid; i < GROWS; i += 168) {
        tile[i][140] = 0.0f; tile[i][141] = 0.0f;
        tile[i][142] = 0.0f; tile[i][143] = 0.0f;
    }
    __syncthreads();

    float* outp = g_pre2 + (size_t)dir * ((size_t)BB * TT * G2)
                + row0 * G2 + idx;
    for (int r = 0; r < GROWS; r++) {
        const ulonglong2* in = (const ulonglong2*)&tile[r][72 * e];
        u64 a0 = pack2(bias, 0.0f), a1 = 0ull, a2 = 0ull, a3 = 0ull;
        #pragma unroll
        for (int k = 0; k < 9; k++) {
            const ulonglong2 va = in[2 * k];
            const ulonglong2 vb = in[2 * k + 1];
            ffma2(a0, wk[4 * k + 0], va.x);
            ffma2(a1, wk[4 * k + 1], va.y);
            ffma2(a2, wk[4 * k + 2], vb.x);
            ffma2(a3, wk[4 * k + 3], vb.y);
        }
        float lo, hi;
        unpack2(addf2(addf2(a0, a1), addf2(a2, a3)), lo, hi);
        float s = lo + hi;
        s += __shfl_xor_sync(0xffffffffu, s, 1);   // combine halves
        if (e == 0) outp[(size_t)r * G2] = s;
    }
}

// ---------------------------------------------------------------------------
// Layer 2 recurrence: one WARP per (batch, direction). Lane j < 21 owns cell
// j. 8 accumulators (2 per gate) halve the FFMA2 dependency depth 12 -> 6.
// pre2 read as one float4 per step (cell-major), depth-4 prefetch ring.
// ---------------------------------------------------------------------------
__global__ __launch_bounds__(256, 1) void lstm2_kernel(
    const float* __restrict__ whh_f, const float* __restrict__ whh_b)
{
    __shared__ __align__(16) float hsb[8][2][H2P];   // per-warp double-buffered h

    const int lane = threadIdx.x & 31;
    const int w    = threadIdx.x >> 5;
    const int task = blockIdx.x * 8 + w;
    const int b    = task >> 1;
    const int dir  = task & 1;
    const float* whh = dir ? whh_b : whh_f;

    const bool act = (lane < H2);
    const int j = act ? lane : 0;

    // 4 gate rows for cell j; sigmoid rows (g != 2) scaled by 0.5
    u64 wg[4][12];
    #pragma unroll
    for (int g = 0; g < 4; g++) {
        const int r = g * H2 + j;
        const float sc = (g == 2) ? 1.0f : 0.5f;
        #pragma unroll
        for (int k = 0; k < 12; k++) {
            const int c0 = 2 * k, c1 = c0 + 1;
            wg[g][k] = pack2(sc * ((c0 < H2) ? whh[r * H2 + c0] : 0.0f),
                             sc * ((c1 < H2) ? whh[r * H2 + c1] : 0.0f));
        }
    }
    if (lane < H2P) { hsb[w][0][lane] = 0.0f; hsb[w][1][lane] = 0.0f; }
    __syncwarp();

    const int step = dir ? -1 : 1;
    const int tt0  = dir ? (TT - 1) : 0;
    const float* base = g_pre2 + (size_t)dir * ((size_t)BB * TT * G2);

    // depth-4 prefetch ring of pre2 gate quads
    float4 pr[4];
    const float* pfp = base + ((size_t)b * TT + tt0) * G2 + 4 * j;
    const long pstep = (long)step * G2;
    #pragma unroll
    for (int u = 0; u < 4; u++) {
        pr[u] = *(const float4*)pfp;
        pfp += pstep;
    }

    float* op = &g_h2[((size_t)b * TT + tt0) * H22 + dir * H2 + j];
    const long ostep = (long)step * H22;
    float c = 0.0f;
    int cur = 0;

    for (int t0 = 0; t0 < TT; t0 += 4) {
        #pragma unroll
        for (int u = 0; u < 4; u++) {
            const int t = t0 + u;
            const float4 pv = pr[u];
            if (t + 4 < TT) pr[u] = *(const float4*)pfp;
            pfp += pstep;

            const ulonglong2* hp = (const ulonglong2*)&hsb[w][cur][0];
            u64 a0 = 0ull, a0b = 0ull, a1 = 0ull, a1b = 0ull;
            u64 a2 = 0ull, a2b = 0ull, a3 = 0ull, a3b = 0ull;
            #pragma unroll
            for (int kk = 0; kk < 6; kk++) {
                const ulonglong2 hv = hp[kk];
                ffma2(a0,  wg[0][2 * kk],     hv.x);
                ffma2(a0b, wg[0][2 * kk + 1], hv.y);
                ffma2(a1,  wg[1][2 * kk],     hv.x);
                ffma2(a1b, wg[1][2 * kk + 1], hv.y);
                ffma2(a2,  wg[2][2 * kk],     hv.x);
                ffma2(a2b, wg[2][2 * kk + 1], hv.y);
                ffma2(a3,  wg[3][2 * kk],     hv.x);
                ffma2(a3b, wg[3][2 * kk + 1], hv.y);
            }
            float lo, hi;
            unpack2(addf2(a0, a0b), lo, hi); const float ti = pv.x + lo + hi;
            unpack2(addf2(a1, a1b), lo, hi); const float tf = pv.y + lo + hi;
            unpack2(addf2(a2, a2b), lo, hi); const float tg = pv.z + lo + hi;
            unpack2(addf2(a3, a3b), lo, hi); const float to = pv.w + lo + hi;

            const float gi = fmaf(0.5f, tanha(ti), 0.5f);
            const float gf = fmaf(0.5f, tanha(tf), 0.5f);
            const float gg = tanha(tg);
            const float go = fmaf(0.5f, tanha(to), 0.5f);
            c = fmaf(gf, c, gi * gg);
            const float hval = go * tanha(c);

            const int nxt = cur ^ 1;
            if (act) {
                hsb[w][nxt][lane] = hval;
                *op = hval;
            }
            __syncwarp();
            cur = nxt;
            op += ostep;
        }
    }
}

// ---------------------------------------------------------------------------
// Head MLP (R9-proven form): 42 -> 30 relu -> 20 relu -> 1.
// ---------------------------------------------------------------------------
__global__ __launch_bounds__(128) void head_kernel(
    const float* __restrict__ d1w, const float* __restrict__ d1b,
    const float* __restrict__ d2w, const float* __restrict__ d2b,
    const float* __restrict__ ow,  const float* __restrict__ ob,
    float* __restrict__ out)
{
    __shared__ __align__(16) float sv[128 * H22];
    __shared__ __align__(8) float w1[D1 * H22];
    __shared__ float b1[D1];
    __shared__ __align__(8) float w2[D2 * D1];
    __shared__ float b2[D2];
    __shared__ float wo[D2];
    __shared__ float obias;

    const int tid = threadIdx.x;
    const size_t base = (size_t)blockIdx.x * 128 * H22;

    for (int i = tid; i < 128 * H22; i += 128) sv[i] = g_h2[base + i];
    for (int i = tid; i < D1 * H22; i += 128) w1[i] = d1w[i];
    if (tid < D1) b1[tid] = d1b[tid];
    for (int i = tid; i < D2 * D1; i += 128) w2[i] = d2w[i];
    if (tid < D2) { b2[tid] = d2b[tid]; wo[tid] = ow[tid]; }
    if (tid == 0) obias = ob[0];
    __syncthreads();

    u64 v[21];
    const u64* svr = (const u64*)&sv[tid * H22];
    #pragma unroll
    for (int k = 0; k < 21; k++) v[k] = svr[k];

    float a1[D1];
    #pragma unroll
    for (int jj = 0; jj < D1; jj++) {
        const u64* wr = (const u64*)&w1[jj * H22];
        u64 acc0 = pack2(b1[jj], 0.0f), acc1 = 0ull;
        #pragma unroll
        for (int k = 0; k < 21; k += 2) {
            ffma2(acc0, wr[k], v[k]);
            if (k + 1 < 21) ffma2(acc1, wr[k + 1], v[k + 1]);
        }
        float lo, hi;
        unpack2(addf2(acc0, acc1), lo, hi);
        a1[jj] = fmaxf(lo + hi, 0.0f);
    }
    u64 a1p[15];
    #pragma unroll
    for (int k = 0; k < 15; k++) a1p[k] = pack2(a1[2 * k], a1[2 * k + 1]);

    float a2[D2];
    #pragma unroll
    for (int jj = 0; jj < D2; jj++) {
        const u64* wr = (const u64*)&w2[jj * D1];
        u64 acc0 = pack2(b2[jj], 0.0f), acc1 = 0ull;
        #pragma unroll
        for (int k = 0; k < 15; k += 2) {
            ffma2(acc0, wr[k], a1p[k]);
            if (k + 1 < 15) ffma2(acc1, wr[k + 1], a1p[k + 1]);
        }
        float lo, hi;
        unpack2(addf2(acc0, acc1), lo, hi);
        a2[jj] = fmaxf(lo + hi, 0.0f);
    }
    float o = obias;
    #pragma unroll
    for (int k = 0; k < D2; k++) o = fmaf(wo[k], a2[k], o);

    out[(size_t)blockIdx.x * 128 + tid] = o;
}

// ---------------------------------------------------------------------------
extern "C" void kernel_launch(void* const* d_in, const int* in_sizes, int n_in,
                              void* d_out, int out_size)
{
    const float* x       = (const float*)d_in[0];
    const float* wih1_f  = (const float*)d_in[1];
    const float* whh1_f  = (const float*)d_in[2];
    const float* bih1_f  = (const float*)d_in[3];
    const float* bhh1_f  = (const float*)d_in[4];
    const float* wih1_b  = (const float*)d_in[5];
    const float* whh1_b  = (const float*)d_in[6];
    const float* bih1_b  = (const float*)d_in[7];
    const float* bhh1_b  = (const float*)d_in[8];
    const float* wih2_f  = (const float*)d_in[9];
    const float* whh2_f  = (const float*)d_in[10];
    const float* bih2_f  = (const float*)d_in[11];
    const float* bhh2_f  = (const float*)d_in[12];
    const float* wih2_b  = (const float*)d_in[13];
    const float* whh2_b  = (const float*)d_in[14];
    const float* bih2_b  = (const float*)d_in[15];
    const float* bhh2_b  = (const float*)d_in[16];
    const float* d1w     = (const float*)d_in[17];
    const float* d1b     = (const float*)d_in[18];
    const float* d2w     = (const float*)d_in[19];
    const float* d2b     = (const float*)d_in[20];
    const float* ow      = (const float*)d_in[21];
    const float* obv     = (const float*)d_in[22];
    float* out = (float*)d_out;

    dim3 grid_l1(BB, 2);
    lstm1_kernel<<<grid_l1, 288>>>(x, wih1_f, whh1_f, bih1_f, bhh1_f,
                                   wih1_b, whh1_b, bih1_b, bhh1_b);
    dim3 grid_p2((BB * TT) / GROWS, 2);
    pre2_kernel<<<grid_p2, 168>>>(wih2_f, bih2_f, bhh2_f,
                                  wih2_b, bih2_b, bhh2_b);
    lstm2_kernel<<<(BB * 2) / 8, 256>>>(whh2_f, whh2_b);
    head_kernel<<<(BB * TT) / 128, 128>>>(d1w, d1b, d2w, d2b, ow, obv, out);
}

// round 17
// speedup vs baseline: 1.2477x; 1.0661x over previous
#include <cuda_runtime.h>
#include <math.h>

#define BB 512
#define TT 1024
#define FF 8
#define H1 70
#define H1P 72
#define H2 21
#define H2P 24
#define G2 84
#define IN2 140
#define IN2P 144
#define D1 30
#define D2 20
#define H22 42
#define GROWS 64
#define NTILE 4

typedef unsigned long long u64;
typedef unsigned int u32;

// Scratch (allocation-free rule: __device__ globals)
__device__ float g_h1[(size_t)BB * TT * IN2];            // layer-1 bi-output
__device__ float g_h2[(size_t)BB * TT * H22];            // layer-2 bi-output
__device__ float g_pre2[2ull * BB * TT * G2];            // layer-2 input proj (cell-major, i/f/o pre-scaled by 0.5)

__device__ __forceinline__ float tanha(float x) {
    float y;
    asm("tanh.approx.f32 %0, %1;" : "=f"(y) : "f"(x));
    return y;
}

// ---- packed f32x2 helpers -------------------------------------------------
__device__ __forceinline__ u64 pack2(float lo, float hi) {
    u64 r;
    asm("mov.b64 %0, {%1, %2};" : "=l"(r) : "f"(lo), "f"(hi));
    return r;
}
__device__ __forceinline__ void unpack2(u64 v, float& lo, float& hi) {
    asm("mov.b64 {%0, %1}, %2;" : "=f"(lo), "=f"(hi) : "l"(v));
}
__device__ __forceinline__ void ffma2(u64& d, u64 a, u64 b) {
    asm("fma.rn.f32x2 %0, %1, %2, %0;" : "+l"(d) : "l"(a), "l"(b));
}
__device__ __forceinline__ u64 addf2(u64 a, u64 b) {
    u64 r;
    asm("add.rn.f32x2 %0, %1, %2;" : "=l"(r) : "l"(a), "l"(b));
    return r;
}
__device__ __forceinline__ u32 smem_u32(const void* p) {
    u32 a;
    asm("{ .reg .u64 t; cvta.to.shared.u64 t, %1; cvt.u32.u64 %0, t; }"
        : "=r"(a) : "l"(p));
    return a;
}

// ---------------------------------------------------------------------------
// Layer 1 (R12-proven): one CTA per (batch, direction). 288 threads =
// 72 cells x 4 lanes. Lane (j, p, e): cell j, gate-pair p (p=0 -> i,f ;
// p=1 -> g,o), k-half e. Sigmoid-gate rows (i,f,o) pre-scaled by 0.5.
// ---------------------------------------------------------------------------
__global__ __launch_bounds__(288, 2) void lstm1_kernel(
    const float* __restrict__ x,
    const float* __restrict__ wih_f, const float* __restrict__ whh_f,
    const float* __restrict__ bih_f, const float* __restrict__ bhh_f,
    const float* __restrict__ wih_b, const float* __restrict__ whh_b,
    const float* __restrict__ bih_b, const float* __restrict__ bhh_b)
{
    __shared__ __align__(16) float xs[TT * FF];     // 32 KB
    __shared__ __align__(16) float hs[2][H1P];

    const int tid = threadIdx.x;
    const int b   = blockIdx.x;
    const int dir = blockIdx.y;

    const float* wih = dir ? wih_b : wih_f;
    const float* whh = dir ? whh_b : whh_f;
    const float* bih = dir ? bih_b : bih_f;
    const float* bhh = dir ? bhh_b : bhh_f;

    for (int i = tid; i < TT * FF; i += 288)
        xs[i] = x[(size_t)b * TT * FF + i];
    if (tid < H1P) { hs[0][tid] = 0.0f; hs[1][tid] = 0.0f; }

    const int j = tid >> 2;
    const int p = (tid >> 1) & 1;
    const int e = tid & 1;
    const bool act = (j < H1);
    const int r0 = act ? ((2 * p) * H1 + j) : 0;
    const int r1 = act ? ((2 * p + 1) * H1 + j) : 0;
    const float sc0 = (p == 0) ? 0.5f : 1.0f;   // i scaled, g not
    const float sc1 = 0.5f;                     // f, o scaled

    u64 w0[18], w1[18];
    #pragma unroll
    for (int k = 0; k < 18; k++) {
        const int c0 = 36 * e + 2 * k, c1 = c0 + 1;
        w0[k] = pack2(sc0 * ((c0 < H1) ? whh[r0 * H1 + c0] : 0.0f),
                      sc0 * ((c1 < H1) ? whh[r0 * H1 + c1] : 0.0f));
        w1[k] = pack2(sc1 * ((c0 < H1) ? whh[r1 * H1 + c0] : 0.0f),
                      sc1 * ((c1 < H1) ? whh[r1 * H1 + c1] : 0.0f));
    }
    u64 xw0[2], xw1[2];
    #pragma unroll
    for (int k = 0; k < 2; k++) {
        const int c0 = 4 * e + 2 * k;
        xw0[k] = pack2(sc0 * wih[r0 * FF + c0], sc0 * wih[r0 * FF + c0 + 1]);
        xw1[k] = pack2(sc1 * wih[r1 * FF + c0], sc1 * wih[r1 * FF + c0 + 1]);
    }
    const float bias0 = (e == 0) ? sc0 * (bih[r0] + bhh[r0]) : 0.0f;
    const float bias1 = (e == 0) ? sc1 * (bih[r1] + bhh[r1]) : 0.0f;

    float c = 0.0f;
    int cur = 0;
    const int step = dir ? -1 : 1;
    const int tt0 = dir ? (TT - 1) : 0;
    const float* xp = &xs[tt0 * FF + 4 * e];
    float* optr = &g_h1[((size_t)b * TT + tt0) * IN2 + dir * H1 + j];
    const int xstep = step * FF;
    const long ostep = (long)step * IN2;
    __syncthreads();

    // De-phase odd CTAs so co-resident CTAs' tails interleave.
    if (b & 1) {
        float d = bias0 + 1.3f;
        #pragma unroll
        for (int i = 0; i < 200; i++) d = fmaf(d, 0.99991f, 0.00013f);
        if (d == -1234.5678f) hs[0][H1P - 1] = d;   // never true; keeps chain live
    }

    for (int t = 0; t < TT; t++) {
        const ulonglong2 xv = *(const ulonglong2*)xp;
        u64 a00 = pack2(bias0, 0.0f), a01 = 0ull;
        u64 a10 = pack2(bias1, 0.0f), a11 = 0ull;
        ffma2(a00, xw0[0], xv.x); ffma2(a01, xw0[1], xv.y);
        ffma2(a10, xw1[0], xv.x); ffma2(a11, xw1[1], xv.y);

        const ulonglong2* hp = (const ulonglong2*)&hs[cur][36 * e];
        #pragma unroll
        for (int k = 0; k < 9; k++) {
            const ulonglong2 hv = hp[k];
            ffma2(a00, w0[2 * k],     hv.x);
            ffma2(a01, w0[2 * k + 1], hv.y);
            ffma2(a10, w1[2 * k],     hv.x);
            ffma2(a11, w1[2 * k + 1], hv.y);
        }
        float lo, hi;
        unpack2(addf2(a00, a01), lo, hi);
        float s0 = lo + hi;
        unpack2(addf2(a10, a11), lo, hi);
        float s1 = lo + hi;

        s0 += __shfl_xor_sync(0xffffffffu, s0, 1);   // combine k-halves
        s1 += __shfl_xor_sync(0xffffffffu, s1, 1);

        // activate own gate pair, THEN exchange activated values.
        // p=0: act0=sig(i), act1=sig(f); p=1: act0=tanh(g), act1=sig(o)
        const float act0 = p ? tanha(s0) : fmaf(0.5f, tanha(s0), 0.5f);
        const float act1 = fmaf(0.5f, tanha(s1), 0.5f);
        const float x0 = __shfl_xor_sync(0xffffffffu, act0, 2);
        const float x1 = __shfl_xor_sync(0xffffffffu, act1, 2);

        // gi*gg == act0*x0 in BOTH lanes; only f/o need selects
        const float prod = act0 * x0;
        const float gf = p ? x1 : act1;
        const float go = p ? act1 : x1;
        c = fmaf(gf, c, prod);
        const float hval = go * tanha(c);

        const int nxt = cur ^ 1;
        if (((tid & 3) == 0) && act) {
            hs[nxt][j] = hval;
            *optr = hval;
        }
        __syncthreads();
        cur = nxt;
        xp += xstep;
        optr += ostep;
    }
}

// ---------------------------------------------------------------------------
// pre2 GEMM v6: v4 thread layout (168 threads = 84 gates x 2 halves) with
// cp.async double-buffered tiles. Each CTA processes NTILE=4 tiles of 64
// rows; tile t+1 streams into the other buffer while tile t computes.
// Output cell-major [row][j*4+g], i/f/o rows pre-scaled by 0.5.
// ---------------------------------------------------------------------------
__global__ __launch_bounds__(168, 2) void pre2_kernel(
    const float* __restrict__ wih_f, const float* __restrict__ bih_f,
    const float* __restrict__ bhh_f,
    const float* __restrict__ wih_b, const float* __restrict__ bih_b,
    const float* __restrict__ bhh_b)
{
    __shared__ __align__(16) float tile[2][GROWS][IN2P];   // 73.7 KB

    const int tid = threadIdx.x;
    const int dir = blockIdx.y;
    const float* wih = dir ? wih_b : wih_f;
    const float* bih = dir ? bih_b : bih_f;
    const float* bhh = dir ? bhh_b : bhh_f;

    const int idx = tid >> 1;        // gate index = j*4 + g, 0..83
    const int e   = tid & 1;         // k half
    const int g   = idx & 3;
    const int j   = idx >> 2;
    const int gv  = g * H2 + j;      // row in weight matrix
    const float sc = (g == 2) ? 1.0f : 0.5f;   // tanh gate unscaled

    // half of the input weights: padded cols [72e, 72e+72)
    u64 wk[36];
    #pragma unroll
    for (int k = 0; k < 36; k++) {
        const int c0 = 72 * e + 2 * k, c1 = c0 + 1;
        wk[k] = pack2(sc * ((c0 < IN2) ? wih[gv * IN2 + c0] : 0.0f),
                      sc * ((c1 < IN2) ? wih[gv * IN2 + c1] : 0.0f));
    }
    const float bias = (e == 0) ? sc * (bih[gv] + bhh[gv]) : 0.0f;

    const size_t row_base = (size_t)blockIdx.x * (GROWS * NTILE);

    // zero pad columns of both buffers once (cp.async never writes them)
    for (int bb = 0; bb < 2; bb++)
        for (int i = tid; i < GROWS; i += 168) {
            tile[bb][i][140] = 0.0f; tile[bb][i][141] = 0.0f;
            tile[bb][i][142] = 0.0f; tile[bb][i][143] = 0.0f;
        }

    // async stage of one 64-row tile into buffer buf
    auto stage = [&](int buf, int tc) {
        const float4* src = (const float4*)(g_h1 + (row_base + (size_t)tc * GROWS) * IN2);
        const u32 sbase = smem_u32(&tile[buf][0][0]);
        for (int i = tid; i < GROWS * 35; i += 168) {
            const int r = i / 35, cc = i % 35;
            const u32 daddr = sbase + (u32)(r * IN2P + 4 * cc) * 4u;
            asm volatile("cp.async.cg.shared.global [%0], [%1], 16;"
                         :: "r"(daddr), "l"(src + i) : "memory");
        }
        asm volatile("cp.async.commit_group;" ::: "memory");
    };

    stage(0, 0);

    for (int tc = 0; tc < NTILE; tc++) {
        if (tc + 1 < NTILE) {
            stage((tc + 1) & 1, tc + 1);
            asm volatile("cp.async.wait_group 1;" ::: "memory");
        } else {
            asm volatile("cp.async.wait_group 0;" ::: "memory");
        }
        __syncthreads();

        const int buf = tc & 1;
        float* outp = g_pre2 + (size_t)dir * ((size_t)BB * TT * G2)
                    + (row_base + (size_t)tc * GROWS) * G2 + idx;
        for (int r = 0; r < GROWS; r++) {
            const ulonglong2* in = (const ulonglong2*)&tile[buf][r][72 * e];
            u64 a0 = pack2(bias, 0.0f), a1 = 0ull, a2 = 0ull, a3 = 0ull;
            #pragma unroll
            for (int k = 0; k < 9; k++) {
                const ulonglong2 va = in[2 * k];
                const ulonglong2 vb = in[2 * k + 1];
                ffma2(a0, wk[4 * k + 0], va.x);
                ffma2(a1, wk[4 * k + 1], va.y);
                ffma2(a2, wk[4 * k + 2], vb.x);
                ffma2(a3, wk[4 * k + 3], vb.y);
            }
            float lo, hi;
            unpack2(addf2(addf2(a0, a1), addf2(a2, a3)), lo, hi);
            float s = lo + hi;
            s += __shfl_xor_sync(0xffffffffu, s, 1);   // combine halves
            if (e == 0) outp[(size_t)r * G2] = s;
        }
        __syncthreads();   // compute done before next stage overwrites buf
    }
}

// ---------------------------------------------------------------------------
// Layer 2 recurrence (R15-proven): one WARP per (batch, direction). Lane
// j < 21 owns cell j; 8 accumulators halve the FFMA2 dependency depth.
// pre2 read as one float4 per step (cell-major), depth-4 prefetch ring.
// ---------------------------------------------------------------------------
__global__ __launch_bounds__(256, 1) void lstm2_kernel(
    const float* __restrict__ whh_f, const float* __restrict__ whh_b)
{
    __shared__ __align__(16) float hsb[8][2][H2P];   // per-warp double-buffered h

    const int lane = threadIdx.x & 31;
    const int w    = threadIdx.x >> 5;
    const int task = blockIdx.x * 8 + w;
    const int b    = task >> 1;
    const int dir  = task & 1;
    const float* whh = dir ? whh_b : whh_f;

    const bool act = (lane < H2);
    const int j = act ? lane : 0;

    // 4 gate rows for cell j; sigmoid rows (g != 2) scaled by 0.5
    u64 wg[4][12];
    #pragma unroll
    for (int g = 0; g < 4; g++) {
        const int r = g * H2 + j;
        const float sc = (g == 2) ? 1.0f : 0.5f;
        #pragma unroll
        for (int k = 0; k < 12; k++) {
            const int c0 = 2 * k, c1 = c0 + 1;
            wg[g][k] = pack2(sc * ((c0 < H2) ? whh[r * H2 + c0] : 0.0f),
                             sc * ((c1 < H2) ? whh[r * H2 + c1] : 0.0f));
        }
    }
    if (lane < H2P) { hsb[w][0][lane] = 0.0f; hsb[w][1][lane] = 0.0f; }
    __syncwarp();

    const int step = dir ? -1 : 1;
    const int tt0  = dir ? (TT - 1) : 0;
    const float* base = g_pre2 + (size_t)dir * ((size_t)BB * TT * G2);

    // depth-4 prefetch ring of pre2 gate quads
    float4 pr[4];
    const float* pfp = base + ((size_t)b * TT + tt0) * G2 + 4 * j;
    const long pstep = (long)step * G2;
    #pragma unroll
    for (int u = 0; u < 4; u++) {
        pr[u] = *(const float4*)pfp;
        pfp += pstep;
    }

    float* op = &g_h2[((size_t)b * TT + tt0) * H22 + dir * H2 + j];
    const long ostep = (long)step * H22;
    float c = 0.0f;
    int cur = 0;

    for (int t0 = 0; t0 < TT; t0 += 4) {
        #pragma unroll
        for (int u = 0; u < 4; u++) {
            const int t = t0 + u;
            const float4 pv = pr[u];
            if (t + 4 < TT) pr[u] = *(const float4*)pfp;
            pfp += pstep;

            const ulonglong2* hp = (const ulonglong2*)&hsb[w][cur][0];
            u64 a0 = 0ull, a0b = 0ull, a1 = 0ull, a1b = 0ull;
            u64 a2 = 0ull, a2b = 0ull, a3 = 0ull, a3b = 0ull;
            #pragma unroll
            for (int kk = 0; kk < 6; kk++) {
                const ulonglong2 hv = hp[kk];
                ffma2(a0,  wg[0][2 * kk],     hv.x);
                ffma2(a0b, wg[0][2 * kk + 1], hv.y);
                ffma2(a1,  wg[1][2 * kk],     hv.x);
                ffma2(a1b, wg[1][2 * kk + 1], hv.y);
                ffma2(a2,  wg[2][2 * kk],     hv.x);
                ffma2(a2b, wg[2][2 * kk + 1], hv.y);
                ffma2(a3,  wg[3][2 * kk],     hv.x);
                ffma2(a3b, wg[3][2 * kk + 1], hv.y);
            }
            float lo, hi;
            unpack2(addf2(a0, a0b), lo, hi); const float ti = pv.x + lo + hi;
            unpack2(addf2(a1, a1b), lo, hi); const float tf = pv.y + lo + hi;
            unpack2(addf2(a2, a2b), lo, hi); const float tg = pv.z + lo + hi;
            unpack2(addf2(a3, a3b), lo, hi); const float to = pv.w + lo + hi;

            const float gi = fmaf(0.5f, tanha(ti), 0.5f);
            const float gf = fmaf(0.5f, tanha(tf), 0.5f);
            const float gg = tanha(tg);
            const float go = fmaf(0.5f, tanha(to), 0.5f);
            c = fmaf(gf, c, gi * gg);
            const float hval = go * tanha(c);

            const int nxt = cur ^ 1;
            if (act) {
                hsb[w][nxt][lane] = hval;
                *op = hval;
            }
            __syncwarp();
            cur = nxt;
            op += ostep;
        }
    }
}

// ---------------------------------------------------------------------------
// Head MLP (R9-proven form): 42 -> 30 relu -> 20 relu -> 1.
// ---------------------------------------------------------------------------
__global__ __launch_bounds__(128) void head_kernel(
    const float* __restrict__ d1w, const float* __restrict__ d1b,
    const float* __restrict__ d2w, const float* __restrict__ d2b,
    const float* __restrict__ ow,  const float* __restrict__ ob,
    float* __restrict__ out)
{
    __shared__ __align__(16) float sv[128 * H22];
    __shared__ __align__(8) float w1[D1 * H22];
    __shared__ float b1[D1];
    __shared__ __align__(8) float w2[D2 * D1];
    __shared__ float b2[D2];
    __shared__ float wo[D2];
    __shared__ float obias;

    const int tid = threadIdx.x;
    const size_t base = (size_t)blockIdx.x * 128 * H22;

    for (int i = tid; i < 128 * H22; i += 128) sv[i] = g_h2[base + i];
    for (int i = tid; i < D1 * H22; i += 128) w1[i] = d1w[i];
    if (tid < D1) b1[tid] = d1b[tid];
    for (int i = tid; i < D2 * D1; i += 128) w2[i] = d2w[i];
    if (tid < D2) { b2[tid] = d2b[tid]; wo[tid] = ow[tid]; }
    if (tid == 0) obias = ob[0];
    __syncthreads();

    u64 v[21];
    const u64* svr = (const u64*)&sv[tid * H22];
    #pragma unroll
    for (int k = 0; k < 21; k++) v[k] = svr[k];

    float a1[D1];
    #pragma unroll
    for (int jj = 0; jj < D1; jj++) {
        const u64* wr = (const u64*)&w1[jj * H22];
        u64 acc0 = pack2(b1[jj], 0.0f), acc1 = 0ull;
        #pragma unroll
        for (int k = 0; k < 21; k += 2) {
            ffma2(acc0, wr[k], v[k]);
            if (k + 1 < 21) ffma2(acc1, wr[k + 1], v[k + 1]);
        }
        float lo, hi;
        unpack2(addf2(acc0, acc1), lo, hi);
        a1[jj] = fmaxf(lo + hi, 0.0f);
    }
    u64 a1p[15];
    #pragma unroll
    for (int k = 0; k < 15; k++) a1p[k] = pack2(a1[2 * k], a1[2 * k + 1]);

    float a2[D2];
    #pragma unroll
    for (int jj = 0; jj < D2; jj++) {
        const u64* wr = (const u64*)&w2[jj * D1];
        u64 acc0 = pack2(b2[jj], 0.0f), acc1 = 0ull;
        #pragma unroll
        for (int k = 0; k < 15; k += 2) {
            ffma2(acc0, wr[k], a1p[k]);
            if (k + 1 < 15) ffma2(acc1, wr[k + 1], a1p[k + 1]);
        }
        float lo, hi;
        unpack2(addf2(acc0, acc1), lo, hi);
        a2[jj] = fmaxf(lo + hi, 0.0f);
    }
    float o = obias;
    #pragma unroll
    for (int k = 0; k < D2; k++) o = fmaf(wo[k], a2[k], o);

    out[(size_t)blockIdx.x * 128 + tid] = o;
}

// ---------------------------------------------------------------------------
extern "C" void kernel_launch(void* const* d_in, const int* in_sizes, int n_in,
                              void* d_out, int out_size)
{
    const float* x       = (const float*)d_in[0];
    const float* wih1_f  = (const float*)d_in[1];
    const float* whh1_f  = (const float*)d_in[2];
    const float* bih1_f  = (const float*)d_in[3];
    const float* bhh1_f  = (const float*)d_in[4];
    const float* wih1_b  = (const float*)d_in[5];
    const float* whh1_b  = (const float*)d_in[6];
    const float* bih1_b  = (const float*)d_in[7];
    const float* bhh1_b  = (const float*)d_in[8];
    const float* wih2_f  = (const float*)d_in[9];
    const float* whh2_f  = (const float*)d_in[10];
    const float* bih2_f  = (const float*)d_in[11];
    const float* bhh2_f  = (const float*)d_in[12];
    const float* wih2_b  = (const float*)d_in[13];
    const float* whh2_b  = (const float*)d_in[14];
    const float* bih2_b  = (const float*)d_in[15];
    const float* bhh2_b  = (const float*)d_in[16];
    const float* d1w     = (const float*)d_in[17];
    const float* d1b     = (const float*)d_in[18];
    const float* d2w     = (const float*)d_in[19];
    const float* d2b     = (const float*)d_in[20];
    const float* ow      = (const float*)d_in[21];
    const float* obv     = (const float*)d_in[22];
    float* out = (float*)d_out;

    dim3 grid_l1(BB, 2);
    lstm1_kernel<<<grid_l1, 288>>>(x, wih1_f, whh1_f, bih1_f, bhh1_f,
                                   wih1_b, whh1_b, bih1_b, bhh1_b);
    dim3 grid_p2((BB * TT) / (GROWS * NTILE), 2);
    pre2_kernel<<<grid_p2, 168>>>(wih2_f, bih2_f, bhh2_f,
                                  wih2_b, bih2_b, bhh2_b);
    lstm2_kernel<<<(BB * 2) / 8, 256>>>(whh2_f, whh2_b);
    head_kernel<<<(BB * TT) / 128, 128>>>(d1w, d1b, d2w, d2b, ow, obv, out);
}